// round 7
// baseline (speedup 1.0000x reference)
#include <cuda_runtime.h>
#include <cuda_bf16.h>
#include <math.h>

#define VOCAB   50257
#define DIM     768
#define RANK    16
#define SCALING 2.0f
#define NTOK    16384

#define NB1     296         // k1 blocks (2 per SM)
#define ROWS1   170         // rows per k1 block (296*170 >= 50257)
#define NBP     296

#define K3B     148
#define K3T     111         // tokens per k3 block (148*111 >= 16384)

typedef unsigned long long u64;

// ---------------- scratch (no allocations allowed) ----------------
__device__ __align__(16) float g_partM[NBP * DIM * RANK];   // [p][d*16+r]
__device__ __align__(16) float g_partE2[NBP * DIM];
__device__ __align__(16) float g_partG[NBP * 256];
__device__ __align__(16) float g_M[DIM * RANK];
__device__ __align__(16) float g_E2[DIM];
__device__ __align__(16) float g_G[256];
__device__ __align__(16) float g_sc[DIM];
__device__ __align__(16) float g_Bs[RANK * DIM];

// ---------------- f32x2 helpers ----------------
__device__ __forceinline__ u64 pack2(float lo, float hi) {
    u64 r;
    asm("mov.b64 %0, {%1, %2};" : "=l"(r) : "f"(lo), "f"(hi));
    return r;
}
__device__ __forceinline__ void unpack2(u64 v, float& lo, float& hi) {
    asm("mov.b64 {%0, %1}, %2;" : "=f"(lo), "=f"(hi) : "l"(v));
}
__device__ __forceinline__ u64 fma2(u64 a, u64 b, u64 c) {
    u64 d;
    asm("fma.rn.f32x2 %0, %1, %2, %3;" : "=l"(d) : "l"(a), "l"(b), "l"(c));
    return d;
}

// =================================================================
// Kernel 1: stream E once. 296 blocks x 384 threads (2 per SM).
// Each thread: 2 columns (float2 loads), f32x2 lanes = RANK-pairs.
// A row-major in shared: 4 LDS.128/row shared across both columns.
// ROLLING 8-deep prefetch: a load is issued before each row's
// compute, keeping ~8 LDG.64 in flight per thread continuously.
// =================================================================
#define PF1 8
__global__ __launch_bounds__(384, 2)
void k1_stats(const float* __restrict__ E, const float* __restrict__ A) {
    __shared__ __align__(16) float shA[ROWS1 * RANK];   // 10.6KB
    const int b    = blockIdx.x;
    const int tid  = threadIdx.x;
    const int v0   = b * ROWS1;
    const int rows = min(ROWS1, VOCAB - v0);   // >= 107

    // stage A chunk row-major (fully coalesced)
    for (int idx = tid; idx < rows * RANK; idx += 384)
        shA[idx] = A[(size_t)v0 * RANK + idx];
    __syncthreads();

    const float2* cp = reinterpret_cast<const float2*>(E + (size_t)v0 * DIM) + tid;

    u64 accM0[8], accM1[8];
#pragma unroll
    for (int q = 0; q < 8; q++) { accM0[q] = 0ull; accM1[q] = 0ull; }
    float accE0 = 0.f, accE1 = 0.f;

    float2 cur[PF1];
#pragma unroll
    for (int k = 0; k < PF1; k++) cur[k] = cp[(size_t)min(k, rows - 1) * (DIM / 2)];

    int base = 0;
    for (; base + PF1 <= rows; base += PF1) {
#pragma unroll
        for (int q = 0; q < PF1; q++) {
            const int i = base + q;
            const float2 e = cur[q];
            // rolling prefetch: issue the i+PF1 load BEFORE computing row i
            cur[q] = cp[(size_t)min(i + PF1, rows - 1) * (DIM / 2)];

            const u64 ed0 = pack2(e.x, e.x);
            const u64 ed1 = pack2(e.y, e.y);
            const ulonglong2* ap = reinterpret_cast<const ulonglong2*>(shA + i * RANK);
#pragma unroll
            for (int q2 = 0; q2 < 4; q2++) {
                ulonglong2 av = ap[q2];                 // LDS.128 (broadcast)
                accM0[2 * q2]     = fma2(av.x, ed0, accM0[2 * q2]);
                accM0[2 * q2 + 1] = fma2(av.y, ed0, accM0[2 * q2 + 1]);
                accM1[2 * q2]     = fma2(av.x, ed1, accM1[2 * q2]);
                accM1[2 * q2 + 1] = fma2(av.y, ed1, accM1[2 * q2 + 1]);
            }
            accE0 = fmaf(e.x, e.x, accE0);
            accE1 = fmaf(e.y, e.y, accE1);
        }
    }
    // tail rows: slots hold rows base..rows-1 (clamped prefetches only
    // ever land in slots beyond the tail count, never consumed)
    for (int i = base; i < rows; i++) {
        const float2 e = cur[i - base];
        const u64 ed0 = pack2(e.x, e.x);
        const u64 ed1 = pack2(e.y, e.y);
        const ulonglong2* ap = reinterpret_cast<const ulonglong2*>(shA + i * RANK);
#pragma unroll
        for (int q2 = 0; q2 < 4; q2++) {
            ulonglong2 av = ap[q2];
            accM0[2 * q2]     = fma2(av.x, ed0, accM0[2 * q2]);
            accM0[2 * q2 + 1] = fma2(av.y, ed0, accM0[2 * q2 + 1]);
            accM1[2 * q2]     = fma2(av.x, ed1, accM1[2 * q2]);
            accM1[2 * q2 + 1] = fma2(av.y, ed1, accM1[2 * q2 + 1]);
        }
        accE0 = fmaf(e.x, e.x, accE0);
        accE1 = fmaf(e.y, e.y, accE1);
    }

    // write partials: cols 2tid, 2tid+1 -> 8 contiguous float4 (128B)
    {
        float4* dstM = reinterpret_cast<float4*>(g_partM + (size_t)b * (DIM * RANK) + (size_t)2 * tid * RANK);
#pragma unroll
        for (int q2 = 0; q2 < 4; q2++) {
            float l0, h0, l1, h1;
            unpack2(accM0[2 * q2], l0, h0);
            unpack2(accM0[2 * q2 + 1], l1, h1);
            dstM[q2] = make_float4(l0, h0, l1, h1);
        }
#pragma unroll
        for (int q2 = 0; q2 < 4; q2++) {
            float l0, h0, l1, h1;
            unpack2(accM1[2 * q2], l0, h0);
            unpack2(accM1[2 * q2 + 1], l1, h1);
            dstM[4 + q2] = make_float4(l0, h0, l1, h1);
        }
    }
    *reinterpret_cast<float2*>(g_partE2 + (size_t)b * DIM + 2 * tid) = make_float2(accE0, accE1);

    // Gram partials (threads 0..255, one (r,r') pair each)
    if (tid < 256) {
        int r = tid >> 4, r2 = tid & 15;
        float g = 0.f;
        for (int i = 0; i < rows; i++)
            g += shA[i * RANK + r] * shA[i * RANK + r2];
        g_partG[b * 256 + tid] = g;
    }
}

// =================================================================
// Kernel 2: deterministic reduction of the 296 partial sets.
// grid 52 x 256 = 13312 = 12288 (M) + 768 (E2) + 256 (G)
// =================================================================
__global__ void k2_reduce() {
    int j = blockIdx.x * 256 + threadIdx.x;
    if (j < DIM * RANK) {
        float s = 0.f;
#pragma unroll 4
        for (int p = 0; p < NBP; p++) s += g_partM[(size_t)p * (DIM * RANK) + j];
        g_M[j] = s;
    } else if (j < DIM * RANK + DIM) {
        int d = j - DIM * RANK;
        float s = 0.f;
#pragma unroll 4
        for (int p = 0; p < NBP; p++) s += g_partE2[p * DIM + d];
        g_E2[d] = s;
    } else {
        int t = j - (DIM * RANK + DIM);
        float s = 0.f;
#pragma unroll 4
        for (int p = 0; p < NBP; p++) s += g_partG[p * 256 + t];
        g_G[t] = s;
    }
}

// =================================================================
// Kernel 2b: sc[d] = mag[d]/norm[d];  Bs[r,d] = s*B[r,d]*sc[d]
// =================================================================
__global__ void k2b_norms(const float* __restrict__ B, const float* __restrict__ mag) {
    int d = blockIdx.x * 256 + threadIdx.x;
    float bb[RANK];
#pragma unroll
    for (int r = 0; r < RANK; r++) bb[r] = B[r * DIM + d];
    float cross = 0.f, quad = 0.f;
#pragma unroll
    for (int r = 0; r < RANK; r++) {
        float t = 0.f;
#pragma unroll
        for (int r2 = 0; r2 < RANK; r2++) t += g_G[r * RANK + r2] * bb[r2];
        quad  += bb[r] * t;
        cross += g_M[d * RANK + r] * bb[r];
    }
    float n2 = g_E2[d] + 2.f * SCALING * cross + SCALING * SCALING * quad;
    float n  = fmaxf(sqrtf(n2), 1e-8f);
    float sc = mag[d] / n;
    g_sc[d] = sc;
#pragma unroll
    for (int r = 0; r < RANK; r++) g_Bs[r * DIM + d] = SCALING * bb[r] * sc;
}

// =================================================================
// Kernel 3: gather. 768 threads = 768 columns, 111 tokens/block.
// Bs as rank-pair f32x2 registers; A rows row-major in shared
// (4 LDS.128/token); ROLLING 8-deep token prefetch.
// =================================================================
#define PF3 8
__global__ __launch_bounds__(768, 1)
void k3_gather(const int* __restrict__ ids, const float* __restrict__ E,
               const float* __restrict__ A, float* __restrict__ out) {
    __shared__ int shT[K3T];
    __shared__ __align__(16) float shA[K3T * RANK];   // ~7KB
    const int b    = blockIdx.x;
    const int tid  = threadIdx.x;
    const int t0   = b * K3T;
    const int ntok = min(K3T, NTOK - t0);             // 67..111

    // Bs rank-pairs + sc for this column
    u64 rb[8];
#pragma unroll
    for (int q = 0; q < 8; q++)
        rb[q] = pack2(g_Bs[(2 * q) * DIM + tid], g_Bs[(2 * q + 1) * DIM + tid]);
    const float sc = g_sc[tid];

    if (tid < ntok) shT[tid] = ids[t0 + tid];
    __syncthreads();
    for (int idx = tid; idx < ntok * RANK; idx += 768)
        shA[idx] = A[(size_t)shT[idx >> 4] * RANK + (idx & 15)];
    __syncthreads();

    const float* Ep = E + tid;

    float cur[PF3];
#pragma unroll
    for (int k = 0; k < PF3; k++)
        cur[k] = Ep[(size_t)shT[min(k, ntok - 1)] * DIM];

    int base = 0;
    for (; base + PF3 <= ntok; base += PF3) {
#pragma unroll
        for (int q = 0; q < PF3; q++) {
            const int i = base + q;
            const float e = cur[q];
            // rolling prefetch
            cur[q] = Ep[(size_t)shT[min(i + PF3, ntok - 1)] * DIM];

            const ulonglong2* ap = reinterpret_cast<const ulonglong2*>(shA + i * RANK);
            u64 acc = 0ull;
#pragma unroll
            for (int q2 = 0; q2 < 4; q2++) {
                ulonglong2 av = ap[q2];                 // LDS.128 (broadcast)
                acc = fma2(av.x, rb[2 * q2], acc);
                acc = fma2(av.y, rb[2 * q2 + 1], acc);
            }
            float lo, hi;
            unpack2(acc, lo, hi);
            out[(size_t)(t0 + i) * DIM + tid] = fmaf(e, sc, lo + hi);
        }
    }
    for (int i = base; i < ntok; i++) {
        const float e = cur[i - base];
        const ulonglong2* ap = reinterpret_cast<const ulonglong2*>(shA + i * RANK);
        u64 acc = 0ull;
#pragma unroll
        for (int q2 = 0; q2 < 4; q2++) {
            ulonglong2 av = ap[q2];
            acc = fma2(av.x, rb[2 * q2], acc);
            acc = fma2(av.y, rb[2 * q2 + 1], acc);
        }
        float lo, hi;
        unpack2(acc, lo, hi);
        out[(size_t)(t0 + i) * DIM + tid] = fmaf(e, sc, lo + hi);
    }
}

// =================================================================
extern "C" void kernel_launch(void* const* d_in, const int* in_sizes, int n_in,
                              void* d_out, int out_size) {
    const int*   ids = (const int*)d_in[0];    // [8,2048] int32
    const float* E   = (const float*)d_in[1];  // [50257,768]
    const float* A   = (const float*)d_in[2];  // [50257,16]
    const float* B   = (const float*)d_in[3];  // [16,768]
    const float* mag = (const float*)d_in[4];  // [768]
    float* out = (float*)d_out;                // [8,2048,768] fp32

    k1_stats <<<NB1, 384>>>(E, A);
    k2_reduce<<<52, 256>>>();
    k2b_norms<<<3, 256>>>(B, mag);
    k3_gather<<<K3B, 768>>>(ids, E, A, out);
}

// round 8
// speedup vs baseline: 1.0471x; 1.0471x over previous
#include <cuda_runtime.h>
#include <cuda_bf16.h>
#include <math.h>

#define VOCAB   50257
#define DIM     768
#define RANK    16
#define SCALING 2.0f
#define NTOK    16384

#define NB1     296         // k1 blocks (2 per SM)
#define ROWS1   170         // rows per k1 block (296*170 >= 50257)
#define NBP     296

#define K3B     148
#define K3T     111         // tokens per k3 block (148*111 >= 16384)

#define PF1     6
#define PF3     4

typedef unsigned long long u64;

// ---------------- scratch (no allocations allowed) ----------------
__device__ __align__(16) float g_partM[NBP * DIM * RANK];   // [p][d*16+r]
__device__ __align__(16) float g_partE2[NBP * DIM];
__device__ __align__(16) float g_partG[NBP * 256];
__device__ __align__(16) float g_M[DIM * RANK];
__device__ __align__(16) float g_E2[DIM];
__device__ __align__(16) float g_G[256];
__device__ __align__(16) float g_sc[DIM];
__device__ __align__(16) float g_Bs[RANK * DIM];

// ---------------- f32x2 helpers ----------------
__device__ __forceinline__ u64 pack2(float lo, float hi) {
    u64 r;
    asm("mov.b64 %0, {%1, %2};" : "=l"(r) : "f"(lo), "f"(hi));
    return r;
}
__device__ __forceinline__ void unpack2(u64 v, float& lo, float& hi) {
    asm("mov.b64 {%0, %1}, %2;" : "=f"(lo), "=f"(hi) : "l"(v));
}
__device__ __forceinline__ u64 fma2(u64 a, u64 b, u64 c) {
    u64 d;
    asm("fma.rn.f32x2 %0, %1, %2, %3;" : "=l"(d) : "l"(a), "l"(b), "l"(c));
    return d;
}

// =================================================================
// Kernel 1: stream E once. 296 blocks x 192 threads (2/SM).
// Each thread owns FOUR columns (one float4 per row): the 64B of
// A broadcast per row is amortized over 4 outputs -> crossbar
// return traffic drops 4x vs 1-col/thread. f32x2 lanes=RANK-pairs.
// =================================================================
__global__ __launch_bounds__(192, 2)
void k1_stats(const float* __restrict__ E, const float* __restrict__ A) {
    __shared__ __align__(16) float shA[ROWS1 * RANK];   // 10.6KB
    const int b    = blockIdx.x;
    const int tid  = threadIdx.x;
    const int v0   = b * ROWS1;
    const int rows = min(ROWS1, VOCAB - v0);   // >= 107, always > 0

    for (int idx = tid; idx < rows * RANK; idx += 192)
        shA[idx] = A[(size_t)v0 * RANK + idx];
    __syncthreads();

    const float4* cp = reinterpret_cast<const float4*>(E + (size_t)v0 * DIM) + tid;

    u64 accM[4][8];
#pragma unroll
    for (int c = 0; c < 4; c++)
#pragma unroll
        for (int q = 0; q < 8; q++) accM[c][q] = 0ull;
    float accE[4] = {0.f, 0.f, 0.f, 0.f};

    float4 cur[PF1];
#pragma unroll
    for (int k = 0; k < PF1; k++) cur[k] = cp[(size_t)min(k, rows - 1) * (DIM / 4)];

    int base = 0;
    for (; base + PF1 <= rows; base += PF1) {
#pragma unroll
        for (int q = 0; q < PF1; q++) {
            const int i = base + q;
            const float4 e = cur[q];
            cur[q] = cp[(size_t)min(i + PF1, rows - 1) * (DIM / 4)];  // rolling prefetch

            const ulonglong2* ap = reinterpret_cast<const ulonglong2*>(shA + i * RANK);
            const ulonglong2 av0 = ap[0], av1 = ap[1], av2 = ap[2], av3 = ap[3];
            const float ec[4] = {e.x, e.y, e.z, e.w};
#pragma unroll
            for (int c = 0; c < 4; c++) {
                const u64 ed = pack2(ec[c], ec[c]);
                accM[c][0] = fma2(av0.x, ed, accM[c][0]);
                accM[c][1] = fma2(av0.y, ed, accM[c][1]);
                accM[c][2] = fma2(av1.x, ed, accM[c][2]);
                accM[c][3] = fma2(av1.y, ed, accM[c][3]);
                accM[c][4] = fma2(av2.x, ed, accM[c][4]);
                accM[c][5] = fma2(av2.y, ed, accM[c][5]);
                accM[c][6] = fma2(av3.x, ed, accM[c][6]);
                accM[c][7] = fma2(av3.y, ed, accM[c][7]);
                accE[c] = fmaf(ec[c], ec[c], accE[c]);
            }
        }
    }
    for (int i = base; i < rows; i++) {
        const float4 e = cur[i - base];
        const ulonglong2* ap = reinterpret_cast<const ulonglong2*>(shA + i * RANK);
        const ulonglong2 av0 = ap[0], av1 = ap[1], av2 = ap[2], av3 = ap[3];
        const float ec[4] = {e.x, e.y, e.z, e.w};
#pragma unroll
        for (int c = 0; c < 4; c++) {
            const u64 ed = pack2(ec[c], ec[c]);
            accM[c][0] = fma2(av0.x, ed, accM[c][0]);
            accM[c][1] = fma2(av0.y, ed, accM[c][1]);
            accM[c][2] = fma2(av1.x, ed, accM[c][2]);
            accM[c][3] = fma2(av1.y, ed, accM[c][3]);
            accM[c][4] = fma2(av2.x, ed, accM[c][4]);
            accM[c][5] = fma2(av2.y, ed, accM[c][5]);
            accM[c][6] = fma2(av3.x, ed, accM[c][6]);
            accM[c][7] = fma2(av3.y, ed, accM[c][7]);
            accE[c] = fmaf(ec[c], ec[c], accE[c]);
        }
    }

    // write partials: cols 4tid..4tid+3 -> 16 contiguous float4 (256B)
    {
        float4* dstM = reinterpret_cast<float4*>(g_partM + (size_t)b * (DIM * RANK) + (size_t)4 * tid * RANK);
#pragma unroll
        for (int c = 0; c < 4; c++)
#pragma unroll
            for (int q2 = 0; q2 < 4; q2++) {
                float l0, h0, l1, h1;
                unpack2(accM[c][2 * q2], l0, h0);
                unpack2(accM[c][2 * q2 + 1], l1, h1);
                dstM[c * 4 + q2] = make_float4(l0, h0, l1, h1);
            }
    }
    *reinterpret_cast<float4*>(g_partE2 + (size_t)b * DIM + 4 * tid) =
        make_float4(accE[0], accE[1], accE[2], accE[3]);

    // Gram partials (256 pairs over 192 threads)
    for (int idx = tid; idx < 256; idx += 192) {
        int r = idx >> 4, r2 = idx & 15;
        float g = 0.f;
        for (int i = 0; i < rows; i++)
            g += shA[i * RANK + r] * shA[i * RANK + r2];
        g_partG[b * 256 + idx] = g;
    }
}

// =================================================================
// Kernel 2: deterministic reduction of the 296 partial sets.
// grid 52 x 256 = 13312 = 12288 (M) + 768 (E2) + 256 (G)
// =================================================================
__global__ void k2_reduce() {
    int j = blockIdx.x * 256 + threadIdx.x;
    if (j < DIM * RANK) {
        float s = 0.f;
#pragma unroll 4
        for (int p = 0; p < NBP; p++) s += g_partM[(size_t)p * (DIM * RANK) + j];
        g_M[j] = s;
    } else if (j < DIM * RANK + DIM) {
        int d = j - DIM * RANK;
        float s = 0.f;
#pragma unroll 4
        for (int p = 0; p < NBP; p++) s += g_partE2[p * DIM + d];
        g_E2[d] = s;
    } else {
        int t = j - (DIM * RANK + DIM);
        float s = 0.f;
#pragma unroll 4
        for (int p = 0; p < NBP; p++) s += g_partG[p * 256 + t];
        g_G[t] = s;
    }
}

// =================================================================
// Kernel 2b: sc[d] = mag[d]/norm[d];  Bs[r,d] = s*B[r,d]*sc[d]
// =================================================================
__global__ void k2b_norms(const float* __restrict__ B, const float* __restrict__ mag) {
    int d = blockIdx.x * 256 + threadIdx.x;
    float bb[RANK];
#pragma unroll
    for (int r = 0; r < RANK; r++) bb[r] = B[r * DIM + d];
    float cross = 0.f, quad = 0.f;
#pragma unroll
    for (int r = 0; r < RANK; r++) {
        float t = 0.f;
#pragma unroll
        for (int r2 = 0; r2 < RANK; r2++) t += g_G[r * RANK + r2] * bb[r2];
        quad  += bb[r] * t;
        cross += g_M[d * RANK + r] * bb[r];
    }
    float n2 = g_E2[d] + 2.f * SCALING * cross + SCALING * SCALING * quad;
    float n  = fmaxf(sqrtf(n2), 1e-8f);
    float sc = mag[d] / n;
    g_sc[d] = sc;
#pragma unroll
    for (int r = 0; r < RANK; r++) g_Bs[r * DIM + d] = SCALING * bb[r] * sc;
}

// =================================================================
// Kernel 3: gather. 384 threads = 192 d-groups (4 cols each) x 2
// token-substreams; 111 tokens/block, grid 148. The 64B of A per
// token is shared across 4 outputs; Bs for all 4 cols lives in
// registers. float4 E gather, STG.128 out, rolling prefetch.
// =================================================================
__global__ __launch_bounds__(384, 1)
void k3_gather(const int* __restrict__ ids, const float* __restrict__ E,
               const float* __restrict__ A, float* __restrict__ out) {
    __shared__ int shT[K3T];
    __shared__ __align__(16) float shA[K3T * RANK];   // ~7KB
    const int b    = blockIdx.x;
    const int tid  = threadIdx.x;
    const int t0   = b * K3T;
    const int ntok = min(K3T, NTOK - t0);             // 67..111

    const int sub  = tid >= 192;
    const int dg   = sub ? tid - 192 : tid;           // column group: cols 4dg..4dg+3
    const int col  = 4 * dg;

    // Bs rank-pairs + sc for the 4 owned columns
    u64 rb[4][8];
#pragma unroll
    for (int c = 0; c < 4; c++)
#pragma unroll
        for (int q = 0; q < 8; q++)
            rb[c][q] = pack2(g_Bs[(2 * q) * DIM + col + c], g_Bs[(2 * q + 1) * DIM + col + c]);
    float scv[4];
#pragma unroll
    for (int c = 0; c < 4; c++) scv[c] = g_sc[col + c];

    if (tid < ntok) shT[tid] = ids[t0 + tid];
    __syncthreads();
    for (int idx = tid; idx < ntok * RANK; idx += 384)
        shA[idx] = A[(size_t)shT[idx >> 4] * RANK + (idx & 15)];
    __syncthreads();

    // token sub-range
    const int n0  = (ntok + 1) >> 1;
    const int i0  = sub ? n0 : 0;
    const int cnt = (sub ? ntok : n0) - i0;           // >= 33

    const float4* Ep = reinterpret_cast<const float4*>(E) + dg;

    float4 cur[PF3];
#pragma unroll
    for (int k = 0; k < PF3; k++)
        cur[k] = Ep[(size_t)shT[i0 + min(k, cnt - 1)] * (DIM / 4)];

    int base = 0;
    for (; base + PF3 <= cnt; base += PF3) {
#pragma unroll
        for (int q = 0; q < PF3; q++) {
            const int j = base + q;
            const int i = i0 + j;
            const float4 e = cur[q];
            cur[q] = Ep[(size_t)shT[i0 + min(j + PF3, cnt - 1)] * (DIM / 4)];  // rolling

            const ulonglong2* ap = reinterpret_cast<const ulonglong2*>(shA + i * RANK);
            const ulonglong2 av0 = ap[0], av1 = ap[1], av2 = ap[2], av3 = ap[3];
            const float ec[4] = {e.x, e.y, e.z, e.w};
            float res[4];
#pragma unroll
            for (int c = 0; c < 4; c++) {
                u64 acc = 0ull;
                acc = fma2(av0.x, rb[c][0], acc);
                acc = fma2(av0.y, rb[c][1], acc);
                acc = fma2(av1.x, rb[c][2], acc);
                acc = fma2(av1.y, rb[c][3], acc);
                acc = fma2(av2.x, rb[c][4], acc);
                acc = fma2(av2.y, rb[c][5], acc);
                acc = fma2(av3.x, rb[c][6], acc);
                acc = fma2(av3.y, rb[c][7], acc);
                float lo, hi;
                unpack2(acc, lo, hi);
                res[c] = fmaf(ec[c], scv[c], lo + hi);
            }
            *reinterpret_cast<float4*>(out + (size_t)(t0 + i) * DIM + col) =
                make_float4(res[0], res[1], res[2], res[3]);
        }
    }
    for (int j = base; j < cnt; j++) {
        const int i = i0 + j;
        const float4 e = cur[j - base];
        const ulonglong2* ap = reinterpret_cast<const ulonglong2*>(shA + i * RANK);
        const ulonglong2 av0 = ap[0], av1 = ap[1], av2 = ap[2], av3 = ap[3];
        const float ec[4] = {e.x, e.y, e.z, e.w};
        float res[4];
#pragma unroll
        for (int c = 0; c < 4; c++) {
            u64 acc = 0ull;
            acc = fma2(av0.x, rb[c][0], acc);
            acc = fma2(av0.y, rb[c][1], acc);
            acc = fma2(av1.x, rb[c][2], acc);
            acc = fma2(av1.y, rb[c][3], acc);
            acc = fma2(av2.x, rb[c][4], acc);
            acc = fma2(av2.y, rb[c][5], acc);
            acc = fma2(av3.x, rb[c][6], acc);
            acc = fma2(av3.y, rb[c][7], acc);
            float lo, hi;
            unpack2(acc, lo, hi);
            res[c] = fmaf(ec[c], scv[c], lo + hi);
        }
        *reinterpret_cast<float4*>(out + (size_t)(t0 + i) * DIM + col) =
            make_float4(res[0], res[1], res[2], res[3]);
    }
}

// =================================================================
extern "C" void kernel_launch(void* const* d_in, const int* in_sizes, int n_in,
                              void* d_out, int out_size) {
    const int*   ids = (const int*)d_in[0];    // [8,2048] int32
    const float* E   = (const float*)d_in[1];  // [50257,768]
    const float* A   = (const float*)d_in[2];  // [50257,16]
    const float* B   = (const float*)d_in[3];  // [16,768]
    const float* mag = (const float*)d_in[4];  // [768]
    float* out = (float*)d_out;                // [8,2048,768] fp32

    k1_stats <<<NB1, 192>>>(E, A);
    k2_reduce<<<52, 256>>>();
    k2b_norms<<<3, 256>>>(B, mag);
    k3_gather<<<K3B, 384>>>(ids, E, A, out);
}